// round 4
// baseline (speedup 1.0000x reference)
#include <cuda_runtime.h>
#include <math.h>

#define BB 8
#define LL 2048
#define DD 512
#define HH 1024
#define CC 64
#define MM (BB*LL)   // 16384
#define NSEG 32
#define SEGL 64

// ---------------- scratch (static device globals; no allocations) ----------------
__device__ float g_x  [MM*DD];
__device__ float g_xn [MM*DD];
__device__ float g_h  [MM*HH];
__device__ float g_abc[MM*192];
__device__ float g_u  [MM*192];
__device__ float g_qn [BB*DD];
__device__ float g_w  [DD*192];          // packed+perm Wa|Wb|Wc (rounded)
__device__ float g_w1c[2*DD*HH];         // rounded+perm stem_w1
__device__ float g_w2c[2*HH*DD];         // rounded+perm stem_w2
__device__ float g_seg[BB*NSEG*6*64];

__device__ __forceinline__ unsigned f2tf(float f) {
    unsigned u;
    asm("cvt.rna.tf32.f32 %0, %1;" : "=r"(u) : "f"(f));
    return u;
}
__device__ __forceinline__ float f2tff(float f) { return __uint_as_float(f2tf(f)); }
__device__ __forceinline__ void cp16(void* dst, const void* src) {
    unsigned d = (unsigned)__cvta_generic_to_shared(dst);
    asm volatile("cp.async.cg.shared.global [%0], [%1], 16;\n" :: "r"(d), "l"(src));
}
__device__ __forceinline__ void cp_commit() {
    asm volatile("cp.async.commit_group;\n");
}
template<int N>
__device__ __forceinline__ void cp_wait() {
    asm volatile("cp.async.wait_group %0;\n" :: "n"(N));
}

// ---------------- fused embedding + first LN ----------------
__global__ void embed_ln_kernel(const int* __restrict__ ids,
                                const float* __restrict__ tok,
                                const float* __restrict__ pos,
                                const float* __restrict__ lw,
                                const float* __restrict__ lb,
                                float* __restrict__ x,
                                float* __restrict__ xn) {
    __shared__ float red[2][4];
    int t  = blockIdx.x;
    int id = ids[t];
    int l  = t & (LL - 1);
    float4 a = ((const float4*)(tok + (size_t)id * DD))[threadIdx.x];
    float4 p = ((const float4*)(pos + (size_t)l  * DD))[threadIdx.x];
    float4 v; v.x = a.x + p.x; v.y = a.y + p.y; v.z = a.z + p.z; v.w = a.w + p.w;
    ((float4*)(x + (size_t)t * DD))[threadIdx.x] = v;
    float s  = v.x + v.y + v.z + v.w;
    float s2 = v.x*v.x + v.y*v.y + v.z*v.z + v.w*v.w;
    #pragma unroll
    for (int o = 16; o; o >>= 1) {
        s  += __shfl_down_sync(0xffffffffu, s,  o);
        s2 += __shfl_down_sync(0xffffffffu, s2, o);
    }
    int warp = threadIdx.x >> 5, lane = threadIdx.x & 31;
    if (!lane) { red[0][warp] = s; red[1][warp] = s2; }
    __syncthreads();
    s  = red[0][0] + red[0][1] + red[0][2] + red[0][3];
    s2 = red[1][0] + red[1][1] + red[1][2] + red[1][3];
    float mean = s * (1.0f / DD);
    float var  = s2 * (1.0f / DD) - mean * mean;
    float inv  = rsqrtf(var + 1e-5f);
    int c = threadIdx.x * 4;
    float4 wv = *(const float4*)(lw + c);
    float4 bv = *(const float4*)(lb + c);
    float4 o;
    o.x = f2tff((v.x - mean) * inv * wv.x + bv.x);
    o.y = f2tff((v.y - mean) * inv * wv.y + bv.y);
    o.z = f2tff((v.z - mean) * inv * wv.z + bv.z);
    o.w = f2tff((v.w - mean) * inv * wv.w + bv.w);
    ((float4*)(xn + (size_t)t * DD))[threadIdx.x] = o;
}

// ---------------- LayerNorm (roundOut: store tf32-rounded) ----------------
__global__ void ln_kernel(const float* __restrict__ x,
                          const float* __restrict__ w,
                          const float* __restrict__ b,
                          float* __restrict__ out,
                          int rowMul, int rowOff, int roundOut) {
    __shared__ float red[2][4];
    size_t inRow = (size_t)blockIdx.x * rowMul + rowOff;
    float4 v = ((const float4*)(x + inRow * DD))[threadIdx.x];
    float s  = v.x + v.y + v.z + v.w;
    float s2 = v.x*v.x + v.y*v.y + v.z*v.z + v.w*v.w;
    #pragma unroll
    for (int o = 16; o; o >>= 1) {
        s  += __shfl_down_sync(0xffffffffu, s,  o);
        s2 += __shfl_down_sync(0xffffffffu, s2, o);
    }
    int warp = threadIdx.x >> 5, lane = threadIdx.x & 31;
    if (!lane) { red[0][warp] = s; red[1][warp] = s2; }
    __syncthreads();
    s  = red[0][0] + red[0][1] + red[0][2] + red[0][3];
    s2 = red[1][0] + red[1][1] + red[1][2] + red[1][3];
    float mean = s * (1.0f / DD);
    float var  = s2 * (1.0f / DD) - mean * mean;
    float inv  = rsqrtf(var + 1e-5f);
    int c = threadIdx.x * 4;
    float4 wv = *(const float4*)(w + c);
    float4 bv = *(const float4*)(b + c);
    float4 o;
    o.x = (v.x - mean) * inv * wv.x + bv.x;
    o.y = (v.y - mean) * inv * wv.y + bv.y;
    o.z = (v.z - mean) * inv * wv.z + bv.z;
    o.w = (v.w - mean) * inv * wv.w + bv.w;
    if (roundOut) {
        o.x = f2tff(o.x); o.y = f2tff(o.y); o.z = f2tff(o.z); o.w = f2tff(o.w);
    }
    ((float4*)(out + (size_t)blockIdx.x * DD))[threadIdx.x] = o;
}

// ---------------- weight prep: tf32-round + column permutation ----------------
// perm within 64-col blocks (for BN=128 GEMMs): j' = (j&7)*8 + (j>>3)
__global__ void prep_w64_kernel(const float* __restrict__ in,
                                float* __restrict__ out, int total, int N) {
    int i = blockIdx.x * 256 + threadIdx.x;
    if (i >= total) return;
    int k = i / N, n = i % N;
    int j = n & 63;
    int jp = ((j & 7) << 3) | (j >> 3);
    out[(size_t)k * N + (n & ~63) + jp] = f2tff(in[i]);
}
// pack Wa|Wb|Wc -> [512][192], perm within 32-col blocks (for BN=64 GEMM)
__global__ void pack_w_kernel(const float* __restrict__ Wa,
                              const float* __restrict__ Wb,
                              const float* __restrict__ Wc,
                              float* __restrict__ W) {
    int i = blockIdx.x * 256 + threadIdx.x;      // 0 .. 512*64-1
    if (i >= DD * 64) return;
    int r = i >> 6, c = i & 63;
    int n0 = c;                                  // true col within class block
    int j = n0 & 31;
    int jp = ((j & 7) << 2) | (j >> 3);
    int cp_ = (n0 & ~31) + jp;
    W[r * 192 + cp_]        = f2tff(Wa[i]);
    W[r * 192 + 64 + cp_]   = f2tff(Wb[i]);
    W[r * 192 + 128 + cp_]  = f2tff(Wc[i]);
}

// ---------------- TF32 tensor-core GEMM, 3-stage cp.async, vectorized B frags ----
// Operands must be pre-tf32-rounded. B must be column-permuted per prep kernels.
// EPI: 1 bias+exact GELU(round), 2 bias+residual add, 3 tanh
template<int BM, int BN, int EPI>
__global__ __launch_bounds__(256, 2)
void tf32gemm_async(const float* __restrict__ A, const float* __restrict__ Bw,
                    const float* __restrict__ bias, float* __restrict__ Cm,
                    int M, int N, int K, int ldc, int colOff) {
    constexpr int BK = 32;
    constexpr int AP = BK + 4;                  // A row stride (floats)
    constexpr int NI = BN / 16;                 // n8 tiles per warp
    constexpr int NV = NI / 4;                  // LDS.128 per k-half (2 or 1)
    constexpr int ASZ = BM * AP;                // floats per A stage
    constexpr int BSZ = BK * BN;                // floats per B stage

    extern __shared__ float sm[];
    float* Asp = sm;                 // 3 * ASZ
    float* Bsp = sm + 3 * ASZ;       // 3 * BSZ

    const int tid  = threadIdx.x;
    const int lane = tid & 31, warp = tid >> 5;
    const int wr   = warp >> 1, wc = warp & 1;
    const int g    = lane >> 2, tig = lane & 3;
    const int rowBase = blockIdx.y * BM;
    const int colBase = blockIdx.x * BN;

    float acc[2][NI][4];
    #pragma unroll
    for (int mi = 0; mi < 2; mi++)
        #pragma unroll
        for (int ni = 0; ni < NI; ni++)
            #pragma unroll
            for (int r = 0; r < 4; r++) acc[mi][ni][r] = 0.f;

    constexpr int A_IT = (BM * BK / 4) / 256;
    constexpr int B_IT = (BK * BN / 4) / 256;
    const int nt = K / BK;

    // smem XOR swizzle (granule units of 4 floats), on row mod 4
    auto bswz = [](int r) -> int {
        if (BN == 128) return ((r & 1) << 2) | ((r >> 1) & 1);  // {0,4,1,5}
        else           return (r & 3) << 1;                      // {0,2,4,6}
    };

    auto issue = [&](int kt) {
        int st = kt % 3;
        int k0 = kt * BK;
        float* As = Asp + st * ASZ;
        float* Bs = Bsp + st * BSZ;
        #pragma unroll
        for (int it = 0; it < A_IT; it++) {
            int idx = tid + it * 256;
            int r = idx / (BK / 4);
            int c = (idx % (BK / 4)) * 4;
            cp16(As + r * AP + c, A + (size_t)(rowBase + r) * K + k0 + c);
        }
        #pragma unroll
        for (int it = 0; it < B_IT; it++) {
            int idx = tid + it * 256;
            int r  = idx / (BN / 4);
            int cg = idx % (BN / 4);
            int pg = cg ^ bswz(r & 3);
            cp16(Bs + r * BN + pg * 4, Bw + (size_t)(k0 + r) * N + colBase + cg * 4);
        }
    };

    issue(0); cp_commit();
    issue(1); cp_commit();

    for (int kt = 0; kt < nt; kt++) {
        if (kt + 2 < nt)      { issue(kt + 2); cp_commit(); cp_wait<2>(); }
        else if (kt + 1 < nt) { cp_wait<1>(); }
        else                  { cp_wait<0>(); }
        __syncthreads();

        const float* As = Asp + (kt % 3) * ASZ;
        const float* Bs = Bsp + (kt % 3) * BSZ;

        #pragma unroll
        for (int kk = 0; kk < BK; kk += 8) {
            unsigned af[2][4];
            #pragma unroll
            for (int mi = 0; mi < 2; mi++) {
                int m0 = wr * 32 + mi * 16 + g;
                af[mi][0] = __float_as_uint(As[(m0    ) * AP + kk + tig    ]);
                af[mi][1] = __float_as_uint(As[(m0 + 8) * AP + kk + tig    ]);
                af[mi][2] = __float_as_uint(As[(m0    ) * AP + kk + tig + 4]);
                af[mi][3] = __float_as_uint(As[(m0 + 8) * AP + kk + tig + 4]);
            }
            unsigned bf[NI][2];
            #pragma unroll
            for (int half = 0; half < 2; half++) {
                int row = kk + tig + half * 4;
                const float* Brow = Bs + row * BN;
                int sw = bswz(tig);
                #pragma unroll
                for (int h = 0; h < NV; h++) {
                    int pg = ((wc * (BN / 8)) + NV * g + h) ^ sw;
                    uint4 v = *(const uint4*)(Brow + pg * 4);
                    bf[h * 4 + 0][half] = v.x;
                    bf[h * 4 + 1][half] = v.y;
                    bf[h * 4 + 2][half] = v.z;
                    bf[h * 4 + 3][half] = v.w;
                }
            }
            #pragma unroll
            for (int mi = 0; mi < 2; mi++)
                #pragma unroll
                for (int ni = 0; ni < NI; ni++) {
                    asm volatile(
                        "mma.sync.aligned.m16n8k8.row.col.f32.tf32.tf32.f32 "
                        "{%0,%1,%2,%3}, {%4,%5,%6,%7}, {%8,%9}, {%0,%1,%2,%3};"
                        : "+f"(acc[mi][ni][0]), "+f"(acc[mi][ni][1]),
                          "+f"(acc[mi][ni][2]), "+f"(acc[mi][ni][3])
                        : "r"(af[mi][0]), "r"(af[mi][1]), "r"(af[mi][2]), "r"(af[mi][3]),
                          "r"(bf[ni][0]), "r"(bf[ni][1]));
                }
        }
        __syncthreads();
    }

    #pragma unroll
    for (int mi = 0; mi < 2; mi++) {
        #pragma unroll
        for (int ni = 0; ni < NI; ni++) {
            int row = rowBase + wr * 32 + mi * 16 + g;
            int col = colBase + wc * (BN / 2) + ni * 8 + tig * 2;
            #pragma unroll
            for (int half = 0; half < 2; half++) {
                int r = row + half * 8;
                float v0 = acc[mi][ni][half * 2 + 0];
                float v1 = acc[mi][ni][half * 2 + 1];
                float2* p = (float2*)(Cm + (size_t)r * ldc + colOff + col);
                if (EPI == 1) {                       // bias + GELU, tf32-rounded out
                    v0 += bias[col];  v1 += bias[col + 1];
                    float2 o;
                    o.x = f2tff(v0 * normcdff(v0));
                    o.y = f2tff(v1 * normcdff(v1));
                    *p = o;
                } else if (EPI == 2) {                // bias + residual add
                    float2 old = *p;
                    float2 o; o.x = old.x + v0 + bias[col];
                    o.y = old.y + v1 + bias[col + 1];
                    *p = o;
                } else {                               // tanh
                    float2 o; o.x = tanhf(v0); o.y = tanhf(v1);
                    *p = o;
                }
            }
        }
    }
}

// ---------------- u = abc @ class^T ----------------
__global__ void u_kernel(const float* __restrict__ abc,
                         const float* __restrict__ cA,
                         const float* __restrict__ cB,
                         const float* __restrict__ cC,
                         float* __restrict__ u) {
    int g = blockIdx.y;
    const float* cls = (g == 0) ? cA : (g == 1) ? cB : cC;
    __shared__ float Ct[64][65];
    __shared__ float At[64][65];
    int tid = threadIdx.x;
    int t0  = blockIdx.x * 64;
    for (int i = tid; i < 4096; i += 256) Ct[i >> 6][i & 63] = cls[i];
    for (int i = tid; i < 4096; i += 256) {
        int tok = i >> 6, r = i & 63;
        At[tok][r] = abc[(size_t)(t0 + tok) * 192 + g * 64 + r];
    }
    __syncthreads();
    int tx = tid & 15, ty = tid >> 4;
    float acc[4][4];
    #pragma unroll
    for (int i = 0; i < 4; i++)
        #pragma unroll
        for (int j = 0; j < 4; j++) acc[i][j] = 0.f;
    for (int r = 0; r < 64; r++) {
        float a[4], b[4];
        #pragma unroll
        for (int i = 0; i < 4; i++) a[i] = At[ty*4 + i][r];
        #pragma unroll
        for (int j = 0; j < 4; j++) b[j] = Ct[tx*4 + j][r];
        #pragma unroll
        for (int i = 0; i < 4; i++)
            #pragma unroll
            for (int j = 0; j < 4; j++) acc[i][j] = fmaf(a[i], b[j], acc[i][j]);
    }
    #pragma unroll
    for (int i = 0; i < 4; i++)
        #pragma unroll
        for (int j = 0; j < 4; j++)
            u[(size_t)(t0 + ty*4 + i) * 192 + g * 64 + tx*4 + j] = acc[i][j];
}

// ---------------- parallel triplet scan ----------------
__global__ void scan_seg_kernel(const float* __restrict__ u,
                                float* __restrict__ segout) {
    int b = blockIdx.x, s = blockIdx.y, c = threadIdx.x;
    int l0 = s * SEGL;
    int l1 = min(l0 + SEGL, LL - 1);
    const float* p = u + ((size_t)b * LL + l0) * 192;
    float pA = 0.f, pB = 0.f, pT = 0.f, AB = 0.f, BC = 0.f, S = 0.f, Cs = 0.f;
    #pragma unroll 4
    for (int l = l0; l < l1; l++) {
        float va = p[c], vb = p[64 + c], vc = p[128 + c];
        p += 192;
        S  = fmaf(vc, pT, S);
        BC = fmaf(vc, pB, BC);
        pT = fmaf(vb, pA, pT);
        AB = fmaf(vb, pA, AB);
        pB += vb;
        pA += va;
        Cs += vc;
    }
    float* o = segout + ((size_t)(b * NSEG + s) * 6) * 64 + c;
    o[0]   = pA;  o[64]  = pB;  o[128] = Cs;
    o[192] = AB;  o[256] = BC;  o[320] = S;
}

__global__ void scan_combine_kernel(const float* __restrict__ segout,
                                    const float* __restrict__ qn,
                                    const float* __restrict__ Wq,
                                    const float* __restrict__ bq,
                                    float* __restrict__ out) {
    int b = blockIdx.x, c = threadIdx.x;
    float PA = 0.f, PAB = 0.f, PE = 0.f, total = 0.f;
    #pragma unroll
    for (int s = 0; s < NSEG; s++) {
        const float* o = segout + ((size_t)(b * NSEG + s) * 6) * 64 + c;
        float A = o[0], B = o[64], C = o[128], AB = o[192], BC = o[256], S = o[320];
        total += S + C * (PE + PAB) + BC * PA;
        PE  = fmaf(B, PA, PE);
        PAB += AB;
        PA  += A;
    }
    float q = 0.f;
    const float* qr = qn + b * DD;
    #pragma unroll 8
    for (int k = 0; k < DD; k++) q = fmaf(qr[k], Wq[k * CC + c], q);
    const float inv_den = (float)(6.0 / (2047.0 * 2046.0 * 2045.0));
    out[b * CC + c] = total * inv_den + q + bq[c];
}

// ---------------- launch ----------------
extern "C" void kernel_launch(void* const* d_in, const int* in_sizes, int n_in,
                              void* d_out, int out_size) {
    const int*   ids       = (const int*)  d_in[0];
    const float* tok_emb   = (const float*)d_in[1];
    const float* pos_emb   = (const float*)d_in[2];
    const float* stem_ln_w = (const float*)d_in[3];
    const float* stem_ln_b = (const float*)d_in[4];
    const float* stem_w1   = (const float*)d_in[5];
    const float* stem_b1   = (const float*)d_in[6];
    const float* stem_w2   = (const float*)d_in[7];
    const float* stem_b2   = (const float*)d_in[8];
    const float* role_ln_w = (const float*)d_in[9];
    const float* role_ln_b = (const float*)d_in[10];
    const float* Wa        = (const float*)d_in[11];
    const float* Wb        = (const float*)d_in[12];
    const float* Wc        = (const float*)d_in[13];
    const float* class_a   = (const float*)d_in[14];
    const float* class_b   = (const float*)d_in[15];
    const float* class_c   = (const float*)d_in[16];
    const float* query_ln_w= (const float*)d_in[17];
    const float* query_ln_b= (const float*)d_in[18];
    const float* Wq        = (const float*)d_in[19];
    const float* bq        = (const float*)d_in[20];
    float* out = (float*)d_out;

    float *xp, *xnp, *hp, *abcp, *up, *qnp, *wp, *w1c, *w2c, *segp;
    cudaGetSymbolAddress((void**)&xp,   g_x);
    cudaGetSymbolAddress((void**)&xnp,  g_xn);
    cudaGetSymbolAddress((void**)&hp,   g_h);
    cudaGetSymbolAddress((void**)&abcp, g_abc);
    cudaGetSymbolAddress((void**)&up,   g_u);
    cudaGetSymbolAddress((void**)&qnp,  g_qn);
    cudaGetSymbolAddress((void**)&wp,   g_w);
    cudaGetSymbolAddress((void**)&w1c,  g_w1c);
    cudaGetSymbolAddress((void**)&w2c,  g_w2c);
    cudaGetSymbolAddress((void**)&segp, g_seg);

    constexpr int SM128 = 3 * (128 * 36 + 32 * 128) * 4;   // 104448
    constexpr int SM64  = 3 * (128 * 36 + 32 * 64)  * 4;   // 79872
    cudaFuncSetAttribute(tf32gemm_async<128,128,1>,
                         cudaFuncAttributeMaxDynamicSharedMemorySize, SM128);
    cudaFuncSetAttribute(tf32gemm_async<128,128,2>,
                         cudaFuncAttributeMaxDynamicSharedMemorySize, SM128);
    cudaFuncSetAttribute(tf32gemm_async<128,64,3>,
                         cudaFuncAttributeMaxDynamicSharedMemorySize, SM64);

    // 0. weight prep (round + permute)
    prep_w64_kernel<<<(2*DD*HH + 255)/256, 256>>>(stem_w1, w1c, 2*DD*HH, HH);
    prep_w64_kernel<<<(2*HH*DD + 255)/256, 256>>>(stem_w2, w2c, 2*HH*DD, DD);
    pack_w_kernel<<<(DD*64 + 255)/256, 256>>>(Wa, Wb, Wc, wp);

    // 1. embedding + LN0 fused
    embed_ln_kernel<<<MM, 128>>>(ids, tok_emb, pos_emb, stem_ln_w, stem_ln_b, xp, xnp);

    // 2. stem blocks
    for (int i = 0; i < 2; i++) {
        if (i > 0)
            ln_kernel<<<MM, 128>>>(xp, stem_ln_w + i*DD, stem_ln_b + i*DD, xnp, 1, 0, 1);
        tf32gemm_async<128,128,1><<<dim3(HH/128, MM/128), 256, SM128>>>(
            xnp, w1c + (size_t)i*DD*HH, stem_b1 + i*HH, hp, MM, HH, DD, HH, 0);
        tf32gemm_async<128,128,2><<<dim3(DD/128, MM/128), 256, SM128>>>(
            hp, w2c + (size_t)i*HH*DD, stem_b2 + i*DD, xp, MM, DD, HH, DD, 0);
    }

    // 3. role LN (rounded)
    ln_kernel<<<MM, 128>>>(xp, role_ln_w, role_ln_b, xnp, 1, 0, 1);

    // 4. abc = tanh(xn @ [Wa|Wb|Wc])
    tf32gemm_async<128,64,3><<<dim3(3, MM/128), 256, SM64>>>(
        xnp, wp, nullptr, abcp, MM, 192, DD, 192, 0);

    // 5. u = abc @ class^T
    u_kernel<<<dim3(MM/64, 3), 256>>>(abcp, class_a, class_b, class_c, up);

    // 6. query LN (natural, not rounded)
    ln_kernel<<<BB, 128>>>(xp, query_ln_w, query_ln_b, qnp, LL, LL - 1, 0);

    // 7. parallel triplet scan + combine
    scan_seg_kernel<<<dim3(BB, NSEG), 64>>>(up, segp);
    scan_combine_kernel<<<BB, CC>>>(segp, qnp, Wq, bq, out);
}

// round 5
// speedup vs baseline: 1.3811x; 1.3811x over previous
#include <cuda_runtime.h>
#include <cuda_fp16.h>
#include <math.h>

#define BB 8
#define LL 2048
#define DD 512
#define HH 1024
#define CC 64
#define MM (BB*LL)   // 16384
#define NSEG 32
#define SEGL 64

// ---------------- scratch (static device globals; no allocations) ----------------
__device__ float  g_x  [MM*DD];      // residual stream (fp32)
__device__ __half g_xn [MM*DD];      // LN outputs (fp16)
__device__ __half g_h  [MM*HH];      // GELU outputs (fp16)
__device__ float  g_abc[MM*192];     // tanh projections
__device__ float  g_u  [MM*192];
__device__ float  g_qn [BB*DD];
__device__ __half g_w1t[2*HH*DD];    // stem_w1 transposed [H][D] fp16
__device__ __half g_w2t[2*DD*HH];    // stem_w2 transposed [D][H] fp16
__device__ __half g_wt [192*DD];     // Wa|Wb|Wc transposed [192][D] fp16
__device__ float  g_seg[BB*NSEG*6*64];

__device__ __forceinline__ void cp16(void* dst, const void* src) {
    unsigned d = (unsigned)__cvta_generic_to_shared(dst);
    asm volatile("cp.async.cg.shared.global [%0], [%1], 16;\n" :: "r"(d), "l"(src));
}
__device__ __forceinline__ void cp_commit() {
    asm volatile("cp.async.commit_group;\n");
}
template<int N>
__device__ __forceinline__ void cp_wait() {
    asm volatile("cp.async.wait_group %0;\n" :: "n"(N));
}

// ---------------- fused embedding + first LN (fp16 xn out) ----------------
__global__ void embed_ln_kernel(const int* __restrict__ ids,
                                const float* __restrict__ tok,
                                const float* __restrict__ pos,
                                const float* __restrict__ lw,
                                const float* __restrict__ lb,
                                float* __restrict__ x,
                                __half* __restrict__ xn) {
    __shared__ float red[2][4];
    int t  = blockIdx.x;
    int id = ids[t];
    int l  = t & (LL - 1);
    float4 a = ((const float4*)(tok + (size_t)id * DD))[threadIdx.x];
    float4 p = ((const float4*)(pos + (size_t)l  * DD))[threadIdx.x];
    float4 v; v.x = a.x + p.x; v.y = a.y + p.y; v.z = a.z + p.z; v.w = a.w + p.w;
    ((float4*)(x + (size_t)t * DD))[threadIdx.x] = v;
    float s  = v.x + v.y + v.z + v.w;
    float s2 = v.x*v.x + v.y*v.y + v.z*v.z + v.w*v.w;
    #pragma unroll
    for (int o = 16; o; o >>= 1) {
        s  += __shfl_down_sync(0xffffffffu, s,  o);
        s2 += __shfl_down_sync(0xffffffffu, s2, o);
    }
    int warp = threadIdx.x >> 5, lane = threadIdx.x & 31;
    if (!lane) { red[0][warp] = s; red[1][warp] = s2; }
    __syncthreads();
    s  = red[0][0] + red[0][1] + red[0][2] + red[0][3];
    s2 = red[1][0] + red[1][1] + red[1][2] + red[1][3];
    float mean = s * (1.0f / DD);
    float var  = s2 * (1.0f / DD) - mean * mean;
    float inv  = rsqrtf(var + 1e-5f);
    int c = threadIdx.x * 4;
    float4 wv = *(const float4*)(lw + c);
    float4 bv = *(const float4*)(lb + c);
    __half2 h0 = __floats2half2_rn((v.x - mean) * inv * wv.x + bv.x,
                                   (v.y - mean) * inv * wv.y + bv.y);
    __half2 h1 = __floats2half2_rn((v.z - mean) * inv * wv.z + bv.z,
                                   (v.w - mean) * inv * wv.w + bv.w);
    *(__half2*)(xn + (size_t)t * DD + c)     = h0;
    *(__half2*)(xn + (size_t)t * DD + c + 2) = h1;
}

// ---------------- LayerNorm; HALF_OUT selects output type ----------------
template<int HALF_OUT>
__global__ void ln_kernel(const float* __restrict__ x,
                          const float* __restrict__ w,
                          const float* __restrict__ b,
                          void* __restrict__ outv,
                          int rowMul, int rowOff) {
    __shared__ float red[2][4];
    size_t inRow = (size_t)blockIdx.x * rowMul + rowOff;
    float4 v = ((const float4*)(x + inRow * DD))[threadIdx.x];
    float s  = v.x + v.y + v.z + v.w;
    float s2 = v.x*v.x + v.y*v.y + v.z*v.z + v.w*v.w;
    #pragma unroll
    for (int o = 16; o; o >>= 1) {
        s  += __shfl_down_sync(0xffffffffu, s,  o);
        s2 += __shfl_down_sync(0xffffffffu, s2, o);
    }
    int warp = threadIdx.x >> 5, lane = threadIdx.x & 31;
    if (!lane) { red[0][warp] = s; red[1][warp] = s2; }
    __syncthreads();
    s  = red[0][0] + red[0][1] + red[0][2] + red[0][3];
    s2 = red[1][0] + red[1][1] + red[1][2] + red[1][3];
    float mean = s * (1.0f / DD);
    float var  = s2 * (1.0f / DD) - mean * mean;
    float inv  = rsqrtf(var + 1e-5f);
    int c = threadIdx.x * 4;
    float4 wv = *(const float4*)(w + c);
    float4 bv = *(const float4*)(b + c);
    float o0 = (v.x - mean) * inv * wv.x + bv.x;
    float o1 = (v.y - mean) * inv * wv.y + bv.y;
    float o2 = (v.z - mean) * inv * wv.z + bv.z;
    float o3 = (v.w - mean) * inv * wv.w + bv.w;
    if (HALF_OUT) {
        __half* out = (__half*)outv;
        *(__half2*)(out + (size_t)blockIdx.x * DD + c)     = __floats2half2_rn(o0, o1);
        *(__half2*)(out + (size_t)blockIdx.x * DD + c + 2) = __floats2half2_rn(o2, o3);
    } else {
        float* out = (float*)outv;
        float4 o; o.x = o0; o.y = o1; o.z = o2; o.w = o3;
        ((float4*)(out + (size_t)blockIdx.x * DD))[threadIdx.x] = o;
    }
}

// ---------------- weight prep: transpose [K][N] -> [N][K] fp16 ----------------
__global__ void transp_kernel(const float* __restrict__ in,
                              __half* __restrict__ out, int K, int N) {
    int i = blockIdx.x * 256 + threadIdx.x;          // over K*N
    if (i >= K * N) return;
    int k = i / N, n = i % N;
    out[(size_t)n * K + k] = __float2half_rn(in[i]);
}
// pack Wa|Wb|Wc -> [192][512] fp16 (row = class*64 + c)
__global__ void pack_w_kernel(const float* __restrict__ Wa,
                              const float* __restrict__ Wb,
                              const float* __restrict__ Wc,
                              __half* __restrict__ W) {
    int i = blockIdx.x * 256 + threadIdx.x;          // 0 .. 512*64-1
    if (i >= DD * 64) return;
    int d = i >> 6, c = i & 63;
    W[(size_t)c * DD + d]         = __float2half_rn(Wa[i]);
    W[(size_t)(64 + c) * DD + d]  = __float2half_rn(Wb[i]);
    W[(size_t)(128 + c) * DD + d] = __float2half_rn(Wc[i]);
}

// ---------------- FP16 tensor-core GEMM, 4-stage cp.async ----------------
// A fp16 [M][K] row-major, B fp16 [N][K] row-major (= col-major operand).
// EPI: 1 bias+exact GELU -> half out, 2 bias+residual add -> fp32, 3 tanh -> fp32
template<int BM, int BN, int EPI>
__global__ __launch_bounds__(256, 2)
void h16gemm(const __half* __restrict__ A, const __half* __restrict__ Bw,
             const float* __restrict__ bias, void* __restrict__ Cv,
             int M, int N, int K, int ldc, int colOff) {
    constexpr int BK = 32;
    constexpr int LDA = BK + 8;                 // 40 halves = 80B, conflict-free
    constexpr int NI = BN / 16;
    constexpr int ASZ = BM * LDA;               // halves per A stage
    constexpr int BSZ = BN * LDA;               // halves per B stage
    constexpr int NST = 4;

    extern __shared__ __half smh[];
    __half* Asp = smh;
    __half* Bsp = smh + NST * ASZ;

    const int tid  = threadIdx.x;
    const int lane = tid & 31, warp = tid >> 5;
    const int wr   = warp >> 1, wc = warp & 1;
    const int g    = lane >> 2, tig = lane & 3;
    const int rowBase = blockIdx.y * BM;
    const int colBase = blockIdx.x * BN;

    float acc[2][NI][4];
    #pragma unroll
    for (int mi = 0; mi < 2; mi++)
        #pragma unroll
        for (int ni = 0; ni < NI; ni++)
            #pragma unroll
            for (int r = 0; r < 4; r++) acc[mi][ni][r] = 0.f;

    constexpr int A_IT = (BM * (BK / 8)) / 256;  // cp16 = 8 halves
    constexpr int B_IT = (BN * (BK / 8)) / 256;
    const int nt = K / BK;

    auto issue = [&](int kt) {
        int st = kt % NST;
        int k0 = kt * BK;
        __half* As = Asp + st * ASZ;
        __half* Bs = Bsp + st * BSZ;
        #pragma unroll
        for (int it = 0; it < A_IT; it++) {
            int idx = tid + it * 256;
            int r = idx / (BK / 8);
            int c = (idx % (BK / 8)) * 8;
            cp16(As + r * LDA + c, A + (size_t)(rowBase + r) * K + k0 + c);
        }
        #pragma unroll
        for (int it = 0; it < B_IT; it++) {
            int idx = tid + it * 256;
            int n = idx / (BK / 8);
            int c = (idx % (BK / 8)) * 8;
            cp16(Bs + n * LDA + c, Bw + (size_t)(colBase + n) * K + k0 + c);
        }
    };

    issue(0); cp_commit();
    issue(1); cp_commit();
    issue(2); cp_commit();

    for (int kt = 0; kt < nt; kt++) {
        if (kt + 3 < nt)      { issue(kt + 3); cp_commit(); cp_wait<3>(); }
        else if (kt + 2 < nt) { cp_wait<2>(); }
        else if (kt + 1 < nt) { cp_wait<1>(); }
        else                  { cp_wait<0>(); }
        __syncthreads();

        const __half* As = Asp + (kt % NST) * ASZ;
        const __half* Bs = Bsp + (kt % NST) * BSZ;

        #pragma unroll
        for (int kk = 0; kk < BK; kk += 16) {
            unsigned af[2][4];
            #pragma unroll
            for (int mi = 0; mi < 2; mi++) {
                int m0 = wr * 32 + mi * 16 + g;
                const __half* r0 = As + (size_t)m0 * LDA + kk + tig * 2;
                const __half* r1 = r0 + 8 * LDA;
                af[mi][0] = *(const unsigned*)r0;
                af[mi][1] = *(const unsigned*)r1;
                af[mi][2] = *(const unsigned*)(r0 + 8);
                af[mi][3] = *(const unsigned*)(r1 + 8);
            }
            unsigned bf[NI][2];
            #pragma unroll
            for (int ni = 0; ni < NI; ni++) {
                int n0 = wc * (BN / 2) + ni * 8 + g;
                const __half* br = Bs + (size_t)n0 * LDA + kk + tig * 2;
                bf[ni][0] = *(const unsigned*)br;
                bf[ni][1] = *(const unsigned*)(br + 8);
            }
            #pragma unroll
            for (int mi = 0; mi < 2; mi++)
                #pragma unroll
                for (int ni = 0; ni < NI; ni++) {
                    asm volatile(
                        "mma.sync.aligned.m16n8k16.row.col.f32.f16.f16.f32 "
                        "{%0,%1,%2,%3}, {%4,%5,%6,%7}, {%8,%9}, {%0,%1,%2,%3};"
                        : "+f"(acc[mi][ni][0]), "+f"(acc[mi][ni][1]),
                          "+f"(acc[mi][ni][2]), "+f"(acc[mi][ni][3])
                        : "r"(af[mi][0]), "r"(af[mi][1]), "r"(af[mi][2]), "r"(af[mi][3]),
                          "r"(bf[ni][0]), "r"(bf[ni][1]));
                }
        }
        __syncthreads();
    }

    #pragma unroll
    for (int mi = 0; mi < 2; mi++) {
        #pragma unroll
        for (int ni = 0; ni < NI; ni++) {
            int row = rowBase + wr * 32 + mi * 16 + g;
            int col = colBase + wc * (BN / 2) + ni * 8 + tig * 2;
            #pragma unroll
            for (int half_ = 0; half_ < 2; half_++) {
                int r = row + half_ * 8;
                float v0 = acc[mi][ni][half_ * 2 + 0];
                float v1 = acc[mi][ni][half_ * 2 + 1];
                if (EPI == 1) {                      // bias + exact GELU -> half
                    v0 += bias[col];  v1 += bias[col + 1];
                    __half* p = (__half*)Cv + (size_t)r * ldc + colOff + col;
                    *(__half2*)p = __floats2half2_rn(v0 * normcdff(v0),
                                                     v1 * normcdff(v1));
                } else if (EPI == 2) {               // bias + residual add -> fp32
                    float2* p = (float2*)((float*)Cv + (size_t)r * ldc + colOff + col);
                    float2 old = *p;
                    float2 o; o.x = old.x + v0 + bias[col];
                    o.y = old.y + v1 + bias[col + 1];
                    *p = o;
                } else {                              // tanh -> fp32
                    float2* p = (float2*)((float*)Cv + (size_t)r * ldc + colOff + col);
                    float2 o; o.x = tanhf(v0); o.y = tanhf(v1);
                    *p = o;
                }
            }
        }
    }
}

// ---------------- u = abc @ class^T ----------------
__global__ void u_kernel(const float* __restrict__ abc,
                         const float* __restrict__ cA,
                         const float* __restrict__ cB,
                         const float* __restrict__ cC,
                         float* __restrict__ u) {
    int g = blockIdx.y;
    const float* cls = (g == 0) ? cA : (g == 1) ? cB : cC;
    __shared__ float Ct[64][65];
    __shared__ float At[64][65];
    int tid = threadIdx.x;
    int t0  = blockIdx.x * 64;
    for (int i = tid; i < 4096; i += 256) Ct[i >> 6][i & 63] = cls[i];
    for (int i = tid; i < 4096; i += 256) {
        int tok = i >> 6, r = i & 63;
        At[tok][r] = abc[(size_t)(t0 + tok) * 192 + g * 64 + r];
    }
    __syncthreads();
    int tx = tid & 15, ty = tid >> 4;
    float acc[4][4];
    #pragma unroll
    for (int i = 0; i < 4; i++)
        #pragma unroll
        for (int j = 0; j < 4; j++) acc[i][j] = 0.f;
    for (int r = 0; r < 64; r++) {
        float a[4], b[4];
        #pragma unroll
        for (int i = 0; i < 4; i++) a[i] = At[ty*4 + i][r];
        #pragma unroll
        for (int j = 0; j < 4; j++) b[j] = Ct[tx*4 + j][r];
        #pragma unroll
        for (int i = 0; i < 4; i++)
            #pragma unroll
            for (int j = 0; j < 4; j++) acc[i][j] = fmaf(a[i], b[j], acc[i][j]);
    }
    #pragma unroll
    for (int i = 0; i < 4; i++)
        #pragma unroll
        for (int j = 0; j < 4; j++)
            u[(size_t)(t0 + ty*4 + i) * 192 + g * 64 + tx*4 + j] = acc[i][j];
}

// ---------------- parallel triplet scan ----------------
__global__ void scan_seg_kernel(const float* __restrict__ u,
                                float* __restrict__ segout) {
    int b = blockIdx.x, s = blockIdx.y, c = threadIdx.x;
    int l0 = s * SEGL;
    int l1 = min(l0 + SEGL, LL - 1);
    const float* p = u + ((size_t)b * LL + l0) * 192;
    float pA = 0.f, pB = 0.f, pT = 0.f, AB = 0.f, BC = 0.f, S = 0.f, Cs = 0.f;
    #pragma unroll 4
    for (int l = l0; l < l1; l++) {
        float va = p[c], vb = p[64 + c], vc = p[128 + c];
        p += 192;
        S  = fmaf(vc, pT, S);
        BC = fmaf(vc, pB, BC);
        pT = fmaf(vb, pA, pT);
        AB = fmaf(vb, pA, AB);
        pB += vb;
        pA += va;
        Cs += vc;
    }
    float* o = segout + ((size_t)(b * NSEG + s) * 6) * 64 + c;
    o[0]   = pA;  o[64]  = pB;  o[128] = Cs;
    o[192] = AB;  o[256] = BC;  o[320] = S;
}

__global__ void scan_combine_kernel(const float* __restrict__ segout,
                                    const float* __restrict__ qn,
                                    const float* __restrict__ Wq,
                                    const float* __restrict__ bq,
                                    float* __restrict__ out) {
    int b = blockIdx.x, c = threadIdx.x;
    float PA = 0.f, PAB = 0.f, PE = 0.f, total = 0.f;
    #pragma unroll
    for (int s = 0; s < NSEG; s++) {
        const float* o = segout + ((size_t)(b * NSEG + s) * 6) * 64 + c;
        float A = o[0], B = o[64], C = o[128], AB = o[192], BC = o[256], S = o[320];
        total += S + C * (PE + PAB) + BC * PA;
        PE  = fmaf(B, PA, PE);
        PAB += AB;
        PA  += A;
    }
    float q = 0.f;
    const float* qr = qn + b * DD;
    #pragma unroll 8
    for (int k = 0; k < DD; k++) q = fmaf(qr[k], Wq[k * CC + c], q);
    const float inv_den = (float)(6.0 / (2047.0 * 2046.0 * 2045.0));
    out[b * CC + c] = total * inv_den + q + bq[c];
}

// ---------------- launch ----------------
extern "C" void kernel_launch(void* const* d_in, const int* in_sizes, int n_in,
                              void* d_out, int out_size) {
    const int*   ids       = (const int*)  d_in[0];
    const float* tok_emb   = (const float*)d_in[1];
    const float* pos_emb   = (const float*)d_in[2];
    const float* stem_ln_w = (const float*)d_in[3];
    const float* stem_ln_b = (const float*)d_in[4];
    const float* stem_w1   = (const float*)d_in[5];
    const float* stem_b1   = (const float*)d_in[6];
    const float* stem_w2   = (const float*)d_in[7];
    const float* stem_b2   = (const float*)d_in[8];
    const float* role_ln_w = (const float*)d_in[9];
    const float* role_ln_b = (const float*)d_in[10];
    const float* Wa        = (const float*)d_in[11];
    const float* Wb        = (const float*)d_in[12];
    const float* Wc        = (const float*)d_in[13];
    const float* class_a   = (const float*)d_in[14];
    const float* class_b   = (const float*)d_in[15];
    const float* class_c   = (const float*)d_in[16];
    const float* query_ln_w= (const float*)d_in[17];
    const float* query_ln_b= (const float*)d_in[18];
    const float* Wq        = (const float*)d_in[19];
    const float* bq        = (const float*)d_in[20];
    float* out = (float*)d_out;

    float *xp, *abcp, *up, *qnp, *segp;
    __half *xnp, *hp, *w1t, *w2t, *wt;
    cudaGetSymbolAddress((void**)&xp,   g_x);
    cudaGetSymbolAddress((void**)&xnp,  g_xn);
    cudaGetSymbolAddress((void**)&hp,   g_h);
    cudaGetSymbolAddress((void**)&abcp, g_abc);
    cudaGetSymbolAddress((void**)&up,   g_u);
    cudaGetSymbolAddress((void**)&qnp,  g_qn);
    cudaGetSymbolAddress((void**)&w1t,  g_w1t);
    cudaGetSymbolAddress((void**)&w2t,  g_w2t);
    cudaGetSymbolAddress((void**)&wt,   g_wt);
    cudaGetSymbolAddress((void**)&segp, g_seg);

    constexpr int SM128 = 4 * (128 * 40 + 128 * 40) * 2;   // 81920 B
    constexpr int SM64  = 4 * (128 * 40 + 64 * 40)  * 2;   // 61440 B
    cudaFuncSetAttribute(h16gemm<128,128,1>,
                         cudaFuncAttributeMaxDynamicSharedMemorySize, SM128);
    cudaFuncSetAttribute(h16gemm<128,128,2>,
                         cudaFuncAttributeMaxDynamicSharedMemorySize, SM128);
    cudaFuncSetAttribute(h16gemm<128,64,3>,
                         cudaFuncAttributeMaxDynamicSharedMemorySize, SM64);

    // 0. weight prep: fp16 transpose
    for (int i = 0; i < 2; i++) {
        transp_kernel<<<(DD*HH + 255)/256, 256>>>(
            stem_w1 + (size_t)i*DD*HH, w1t + (size_t)i*HH*DD, DD, HH);
        transp_kernel<<<(HH*DD + 255)/256, 256>>>(
            stem_w2 + (size_t)i*HH*DD, w2t + (size_t)i*DD*HH, HH, DD);
    }
    pack_w_kernel<<<(DD*64 + 255)/256, 256>>>(Wa, Wb, Wc, wt);

    // 1. embedding + LN0 fused
    embed_ln_kernel<<<MM, 128>>>(ids, tok_emb, pos_emb, stem_ln_w, stem_ln_b, xp, xnp);

    // 2. stem blocks
    for (int i = 0; i < 2; i++) {
        if (i > 0)
            ln_kernel<1><<<MM, 128>>>(xp, stem_ln_w + i*DD, stem_ln_b + i*DD, xnp, 1, 0);
        h16gemm<128,128,1><<<dim3(HH/128, MM/128), 256, SM128>>>(
            xnp, w1t + (size_t)i*HH*DD, stem_b1 + i*HH, hp, MM, HH, DD, HH, 0);
        h16gemm<128,128,2><<<dim3(DD/128, MM/128), 256, SM128>>>(
            hp, w2t + (size_t)i*DD*HH, stem_b2 + i*DD, xp, MM, DD, HH, DD, 0);
    }

    // 3. role LN (fp16 out)
    ln_kernel<1><<<MM, 128>>>(xp, role_ln_w, role_ln_b, xnp, 1, 0);

    // 4. abc = tanh(xn @ [Wa|Wb|Wc])
    h16gemm<128,64,3><<<dim3(3, MM/128), 256, SM64>>>(
        xnp, wt, nullptr, abcp, MM, 192, DD, 192, 0);

    // 5. u = abc @ class^T
    u_kernel<<<dim3(MM/64, 3), 256>>>(abcp, class_a, class_b, class_c, up);

    // 6. query LN (fp32 out)
    ln_kernel<0><<<BB, 128>>>(xp, query_ln_w, query_ln_b, qnp, LL, LL - 1);

    // 7. parallel triplet scan + combine
    scan_seg_kernel<<<dim3(BB, NSEG), 64>>>(up, segp);
    scan_combine_kernel<<<BB, CC>>>(segp, qnp, Wq, bq, out);
}

// round 7
// speedup vs baseline: 1.6349x; 1.1837x over previous
#include <cuda_runtime.h>
#include <cuda_fp16.h>
#include <math.h>

#define BB 8
#define LL 2048
#define DD 512
#define HH 1024
#define CC 64
#define MM (BB*LL)   // 16384
#define NSEG 32
#define SEGL 64

// ---------------- scratch (static device globals; no allocations) ----------------
__device__ float  g_x  [MM*DD];      // residual stream (fp32)
__device__ __half g_xn [MM*DD];      // LN outputs (fp16)
__device__ __half g_h  [MM*HH];      // GELU outputs (fp16)
__device__ float  g_abc[MM*192];     // tanh projections
__device__ float  g_u  [MM*192];
__device__ float  g_qn [BB*DD];
__device__ __half g_w1t[2*HH*DD];    // stem_w1 transposed [H][D] fp16
__device__ __half g_w2t[2*DD*HH];    // stem_w2 transposed [D][H] fp16
__device__ __half g_wt [192*DD];     // Wa|Wb|Wc transposed [192][D] fp16
__device__ float  g_seg[BB*NSEG*6*64];

// ---------------- PTX helpers ----------------
__device__ __forceinline__ void cp16g(void* dst, const void* src) {
    unsigned d = (unsigned)__cvta_generic_to_shared(dst);
    asm volatile("cp.async.cg.shared.global [%0], [%1], 16;\n" :: "r"(d), "l"(src));
}
__device__ __forceinline__ void cp_commit() {
    asm volatile("cp.async.commit_group;\n");
}
template<int N>
__device__ __forceinline__ void cp_wait() {
    asm volatile("cp.async.wait_group %0;\n" :: "n"(N));
}
__device__ __forceinline__ void ldsm4(unsigned& r0, unsigned& r1,
                                      unsigned& r2, unsigned& r3, unsigned addr) {
    asm volatile("ldmatrix.sync.aligned.m8n8.x4.shared.b16 {%0,%1,%2,%3}, [%4];"
                 : "=r"(r0), "=r"(r1), "=r"(r2), "=r"(r3) : "r"(addr));
}

// ---------------- fused embedding + first LN (fp16 xn out) ----------------
__global__ void embed_ln_kernel(const int* __restrict__ ids,
                                const float* __restrict__ tok,
                                const float* __restrict__ pos,
                                const float* __restrict__ lw,
                                const float* __restrict__ lb,
                                float* __restrict__ x,
                                __half* __restrict__ xn) {
    __shared__ float red[2][4];
    int t  = blockIdx.x;
    int id = ids[t];
    int l  = t & (LL - 1);
    float4 a = ((const float4*)(tok + (size_t)id * DD))[threadIdx.x];
    float4 p = ((const float4*)(pos + (size_t)l  * DD))[threadIdx.x];
    float4 v; v.x = a.x + p.x; v.y = a.y + p.y; v.z = a.z + p.z; v.w = a.w + p.w;
    ((float4*)(x + (size_t)t * DD))[threadIdx.x] = v;
    float s  = v.x + v.y + v.z + v.w;
    float s2 = v.x*v.x + v.y*v.y + v.z*v.z + v.w*v.w;
    #pragma unroll
    for (int o = 16; o; o >>= 1) {
        s  += __shfl_down_sync(0xffffffffu, s,  o);
        s2 += __shfl_down_sync(0xffffffffu, s2, o);
    }
    int warp = threadIdx.x >> 5, lane = threadIdx.x & 31;
    if (!lane) { red[0][warp] = s; red[1][warp] = s2; }
    __syncthreads();
    s  = red[0][0] + red[0][1] + red[0][2] + red[0][3];
    s2 = red[1][0] + red[1][1] + red[1][2] + red[1][3];
    float mean = s * (1.0f / DD);
    float var  = s2 * (1.0f / DD) - mean * mean;
    float inv  = rsqrtf(var + 1e-5f);
    int c = threadIdx.x * 4;
    float4 wv = *(const float4*)(lw + c);
    float4 bv = *(const float4*)(lb + c);
    __half2 h0 = __floats2half2_rn((v.x - mean) * inv * wv.x + bv.x,
                                   (v.y - mean) * inv * wv.y + bv.y);
    __half2 h1 = __floats2half2_rn((v.z - mean) * inv * wv.z + bv.z,
                                   (v.w - mean) * inv * wv.w + bv.w);
    *(__half2*)(xn + (size_t)t * DD + c)     = h0;
    *(__half2*)(xn + (size_t)t * DD + c + 2) = h1;
}

// ---------------- LayerNorm; HALF_OUT selects output type ----------------
template<int HALF_OUT>
__global__ void ln_kernel(const float* __restrict__ x,
                          const float* __restrict__ w,
                          const float* __restrict__ b,
                          void* __restrict__ outv,
                          int rowMul, int rowOff) {
    __shared__ float red[2][4];
    size_t inRow = (size_t)blockIdx.x * rowMul + rowOff;
    float4 v = ((const float4*)(x + inRow * DD))[threadIdx.x];
    float s  = v.x + v.y + v.z + v.w;
    float s2 = v.x*v.x + v.y*v.y + v.z*v.z + v.w*v.w;
    #pragma unroll
    for (int o = 16; o; o >>= 1) {
        s  += __shfl_down_sync(0xffffffffu, s,  o);
        s2 += __shfl_down_sync(0xffffffffu, s2, o);
    }
    int warp = threadIdx.x >> 5, lane = threadIdx.x & 31;
    if (!lane) { red[0][warp] = s; red[1][warp] = s2; }
    __syncthreads();
    s  = red[0][0] + red[0][1] + red[0][2] + red[0][3];
    s2 = red[1][0] + red[1][1] + red[1][2] + red[1][3];
    float mean = s * (1.0f / DD);
    float var  = s2 * (1.0f / DD) - mean * mean;
    float inv  = rsqrtf(var + 1e-5f);
    int c = threadIdx.x * 4;
    float4 wv = *(const float4*)(w + c);
    float4 bv = *(const float4*)(b + c);
    float o0 = (v.x - mean) * inv * wv.x + bv.x;
    float o1 = (v.y - mean) * inv * wv.y + bv.y;
    float o2 = (v.z - mean) * inv * wv.z + bv.z;
    float o3 = (v.w - mean) * inv * wv.w + bv.w;
    if (HALF_OUT) {
        __half* out = (__half*)outv;
        *(__half2*)(out + (size_t)blockIdx.x * DD + c)     = __floats2half2_rn(o0, o1);
        *(__half2*)(out + (size_t)blockIdx.x * DD + c + 2) = __floats2half2_rn(o2, o3);
    } else {
        float* out = (float*)outv;
        float4 o; o.x = o0; o.y = o1; o.z = o2; o.w = o3;
        ((float4*)(out + (size_t)blockIdx.x * DD))[threadIdx.x] = o;
    }
}

// ---------------- smem-tiled transpose: in[K][N] fp32 -> out[N][K] fp16 ----------
__global__ void transp_kernel(const float* __restrict__ in,
                              __half* __restrict__ out, int K, int N) {
    __shared__ __half t[32][33];
    int n0 = blockIdx.x * 32, k0 = blockIdx.y * 32;
    int tx = threadIdx.x, ty = threadIdx.y;      // 32 x 8
    #pragma unroll
    for (int i = 0; i < 32; i += 8)
        t[ty + i][tx] = __float2half_rn(in[(size_t)(k0 + ty + i) * N + n0 + tx]);
    __syncthreads();
    #pragma unroll
    for (int i = 0; i < 32; i += 8)
        out[(size_t)(n0 + ty + i) * K + k0 + tx] = t[tx][ty + i];
}
// pack Wa|Wb|Wc -> [192][512] fp16 (row = class*64 + c)
__global__ void pack_w_kernel(const float* __restrict__ Wa,
                              const float* __restrict__ Wb,
                              const float* __restrict__ Wc,
                              __half* __restrict__ W) {
    int i = blockIdx.x * 256 + threadIdx.x;
    if (i >= DD * 64) return;
    int d = i >> 6, c = i & 63;
    W[(size_t)c * DD + d]         = __float2half_rn(Wa[i]);
    W[(size_t)(64 + c) * DD + d]  = __float2half_rn(Wb[i]);
    W[(size_t)(128 + c) * DD + d] = __float2half_rn(Wc[i]);
}

// ======= FP16 mma.sync GEMM v2: BK=64, ldmatrix fragments, 2-stage cp.async ======
// A fp16 [M][K] row-major, B fp16 [N][K] row-major. Tile 128x128, 8 warps (4x2).
// EPI: 1 bias+exact GELU -> half out, 2 bias+residual add -> fp32
template<int EPI>
__global__ __launch_bounds__(256, 2)
void h16gemm2(const __half* __restrict__ A, const __half* __restrict__ Bw,
              const float* __restrict__ bias, void* __restrict__ Cv,
              int K, int ldc) {
    constexpr int BM = 128, BN = 128, BK = 64;
    constexpr int LDA = BK + 8;                 // 72 halves = 144B
    constexpr int NI  = BN / 16;                // 8
    constexpr int ASZ = BM * LDA;               // halves per A stage
    constexpr int BSZ = BN * LDA;

    extern __shared__ __half smh[];
    __half* Asp = smh;
    __half* Bsp = smh + 2 * ASZ;

    const int tid  = threadIdx.x;
    const int lane = tid & 31, warp = tid >> 5;
    const int wr   = warp >> 1, wc = warp & 1;
    const int g    = lane >> 2, tig = lane & 3;
    const int rowBase = blockIdx.y * BM;
    const int colBase = blockIdx.x * BN;

    float acc[2][NI][4];
    #pragma unroll
    for (int mi = 0; mi < 2; mi++)
        #pragma unroll
        for (int ni = 0; ni < NI; ni++)
            #pragma unroll
            for (int r = 0; r < 4; r++) acc[mi][ni][r] = 0.f;

    // ldmatrix lane base addresses (bytes, stage 0)
    unsigned aBase[2], bBase[4];
    {
        unsigned a0 = (unsigned)__cvta_generic_to_shared(Asp);
        unsigned b0 = (unsigned)__cvta_generic_to_shared(Bsp);
        #pragma unroll
        for (int mi = 0; mi < 2; mi++) {
            int row = wr * 32 + mi * 16 + (lane & 15);
            int col = (lane >> 4) << 3;
            aBase[mi] = a0 + (row * LDA + col) * 2;
        }
        #pragma unroll
        for (int p = 0; p < 4; p++) {
            int row = wc * 64 + p * 16 + ((lane >> 4) << 3) + (lane & 7);
            int col = ((lane >> 3) & 1) << 3;
            bBase[p] = b0 + (row * LDA + col) * 2;
        }
    }

    const int nt = K / BK;

    auto issue = [&](int kt) {
        int st = kt & 1;
        int k0 = kt * BK;
        __half* As = Asp + st * ASZ;
        __half* Bs = Bsp + st * BSZ;
        #pragma unroll
        for (int it = 0; it < 4; it++) {        // A: 128 rows x 8 chunks / 256 thr
            int idx = tid + it * 256;
            int r = idx >> 3, u = (idx & 7) << 3;
            cp16g(As + r * LDA + u, A + (size_t)(rowBase + r) * K + k0 + u);
        }
        #pragma unroll
        for (int it = 0; it < 4; it++) {
            int idx = tid + it * 256;
            int r = idx >> 3, u = (idx & 7) << 3;
            cp16g(Bs + r * LDA + u, Bw + (size_t)(colBase + r) * K + k0 + u);
        }
    };

    issue(0); cp_commit();

    for (int kt = 0; kt < nt; kt++) {
        if (kt + 1 < nt) { issue(kt + 1); cp_commit(); cp_wait<1>(); }
        else             { cp_wait<0>(); }
        __syncthreads();

        unsigned stOff = (unsigned)((kt & 1) * ASZ * 2);

        #pragma unroll
        for (int kk = 0; kk < BK; kk += 16) {
            unsigned af[2][4];
            #pragma unroll
            for (int mi = 0; mi < 2; mi++)
                ldsm4(af[mi][0], af[mi][1], af[mi][2], af[mi][3],
                      aBase[mi] + stOff + kk * 2);
            unsigned bf[NI][2];
            #pragma unroll
            for (int p = 0; p < 4; p++)
                ldsm4(bf[2*p][0], bf[2*p][1], bf[2*p+1][0], bf[2*p+1][1],
                      bBase[p] + stOff + kk * 2);
            #pragma unroll
            for (int mi = 0; mi < 2; mi++)
                #pragma unroll
                for (int ni = 0; ni < NI; ni++) {
                    asm volatile(
                        "mma.sync.aligned.m16n8k16.row.col.f32.f16.f16.f32 "
                        "{%0,%1,%2,%3}, {%4,%5,%6,%7}, {%8,%9}, {%0,%1,%2,%3};"
                        : "+f"(acc[mi][ni][0]), "+f"(acc[mi][ni][1]),
                          "+f"(acc[mi][ni][2]), "+f"(acc[mi][ni][3])
                        : "r"(af[mi][0]), "r"(af[mi][1]), "r"(af[mi][2]), "r"(af[mi][3]),
                          "r"(bf[ni][0]), "r"(bf[ni][1]));
                }
        }
        __syncthreads();
    }

    #pragma unroll
    for (int mi = 0; mi < 2; mi++) {
        #pragma unroll
        for (int ni = 0; ni < NI; ni++) {
            int row = rowBase + wr * 32 + mi * 16 + g;
            int col = colBase + wc * 64 + ni * 8 + tig * 2;
            #pragma unroll
            for (int half_ = 0; half_ < 2; half_++) {
                int r = row + half_ * 8;
                float v0 = acc[mi][ni][half_ * 2 + 0];
                float v1 = acc[mi][ni][half_ * 2 + 1];
                if (EPI == 1) {                      // bias + exact GELU -> half
                    v0 += bias[col];  v1 += bias[col + 1];
                    __half* p = (__half*)Cv + (size_t)r * ldc + col;
                    *(__half2*)p = __floats2half2_rn(v0 * normcdff(v0),
                                                     v1 * normcdff(v1));
                } else {                             // bias + residual add -> fp32
                    float2* p = (float2*)((float*)Cv + (size_t)r * ldc + col);
                    float2 old = *p;
                    float2 o; o.x = old.x + v0 + bias[col];
                    o.y = old.y + v1 + bias[col + 1];
                    *p = o;
                }
            }
        }
    }
}

// ---------------- FP16 mma.sync GEMM (role projections), 4-stage cp.async --------
template<int BM, int BN>
__global__ __launch_bounds__(256, 2)
void h16gemm_tanh(const __half* __restrict__ A, const __half* __restrict__ Bw,
                  float* __restrict__ Cm, int K, int ldc) {
    constexpr int BK = 32;
    constexpr int LDA = BK + 8;
    constexpr int NI = BN / 16;
    constexpr int ASZ = BM * LDA;
    constexpr int BSZ = BN * LDA;
    constexpr int NST = 4;

    extern __shared__ __half smh[];
    __half* Asp = smh;
    __half* Bsp = smh + NST * ASZ;

    const int tid  = threadIdx.x;
    const int lane = tid & 31, warp = tid >> 5;
    const int wr   = warp >> 1, wc = warp & 1;
    const int g    = lane >> 2, tig = lane & 3;
    const int rowBase = blockIdx.y * BM;
    const int colBase = blockIdx.x * BN;

    float acc[2][NI][4];
    #pragma unroll
    for (int mi = 0; mi < 2; mi++)
        #pragma unroll
        for (int ni = 0; ni < NI; ni++)
            #pragma unroll
            for (int r = 0; r < 4; r++) acc[mi][ni][r] = 0.f;

    constexpr int A_IT = (BM * (BK / 8)) / 256;
    constexpr int B_IT = (BN * (BK / 8)) / 256;
    const int nt = K / BK;

    auto issue = [&](int kt) {
        int st = kt % NST;
        int k0 = kt * BK;
        __half* As = Asp + st * ASZ;
        __half* Bs = Bsp + st * BSZ;
        #pragma unroll
        for (int it = 0; it < A_IT; it++) {
            int idx = tid + it * 256;
            int r = idx / (BK / 8);
            int c = (idx % (BK / 8)) * 8;
            cp16g(As + r * LDA + c, A + (size_t)(rowBase + r) * K + k0 + c);
        }
        #pragma unroll
        for (int it = 0; it < B_IT; it++) {
            int idx = tid + it * 256;
            int n = idx / (BK / 8);
            int c = (idx % (BK / 8)) * 8;
            cp16g(Bs + n * LDA + c, Bw + (size_t)(colBase + n) * K + k0 + c);
        }
    };

    issue(0); cp_commit();
    issue(1); cp_commit();
    issue(2); cp_commit();

    for (int kt = 0; kt < nt; kt++) {
        if (kt + 3 < nt)      { issue(kt + 3); cp_commit(); cp_wait<3>(); }
        else if (kt + 2 < nt) { cp_wait<2>(); }
        else if (kt + 1 < nt) { cp_wait<1>(); }
        else                  { cp_wait<0>(); }
        __syncthreads();

        const __half* As = Asp + (kt % NST) * ASZ;
        const __half* Bs = Bsp + (kt % NST) * BSZ;

        #pragma unroll
        for (int kk = 0; kk < BK; kk += 16) {
            unsigned af[2][4];
            #pragma unroll
            for (int mi = 0; mi < 2; mi++) {
                int m0 = wr * 32 + mi * 16 + g;
                const __half* r0 = As + (size_t)m0 * LDA + kk + tig * 2;
                const __half* r1 = r0 + 8 * LDA;
                af[mi][0] = *(const unsigned*)r0;
                af[mi][1] = *(const unsigned*)r1;
                af[mi][2] = *(const unsigned*)(r0 + 8);
                af[mi][3] = *(const unsigned*)(r1 + 8);
            }
            unsigned bf[NI][2];
            #pragma unroll
            for (int ni = 0; ni < NI; ni++) {
                int n0 = wc * (BN / 2) + ni * 8 + g;
                const __half* br = Bs + (size_t)n0 * LDA + kk + tig * 2;
                bf[ni][0] = *(const unsigned*)br;
                bf[ni][1] = *(const unsigned*)(br + 8);
            }
            #pragma unroll
            for (int mi = 0; mi < 2; mi++)
                #pragma unroll
                for (int ni = 0; ni < NI; ni++) {
                    asm volatile(
                        "mma.sync.aligned.m16n8k16.row.col.f32.f16.f16.f32 "
                        "{%0,%1,%2,%3}, {%4,%5,%6,%7}, {%8,%9}, {%0,%1,%2,%3};"
                        : "+f"(acc[mi][ni][0]), "+f"(acc[mi][ni][1]),
                          "+f"(acc[mi][ni][2]), "+f"(acc[mi][ni][3])
                        : "r"(af[mi][0]), "r"(af[mi][1]), "r"(af[mi][2]), "r"(af[mi][3]),
                          "r"(bf[ni][0]), "r"(bf[ni][1]));
                }
        }
        __syncthreads();
    }

    #pragma unroll
    for (int mi = 0; mi < 2; mi++) {
        #pragma unroll
        for (int ni = 0; ni < NI; ni++) {
            int row = rowBase + wr * 32 + mi * 16 + g;
            int col = colBase + wc * (BN / 2) + ni * 8 + tig * 2;
            #pragma unroll
            for (int half_ = 0; half_ < 2; half_++) {
                int r = row + half_ * 8;
                float v0 = acc[mi][ni][half_ * 2 + 0];
                float v1 = acc[mi][ni][half_ * 2 + 1];
                float2* p = (float2*)(Cm + (size_t)r * ldc + col);
                float2 o; o.x = tanhf(v0); o.y = tanhf(v1);
                *p = o;
            }
        }
    }
}

// ---------------- u = abc @ class^T ----------------
__global__ void u_kernel(const float* __restrict__ abc,
                         const float* __restrict__ cA,
                         const float* __restrict__ cB,
                         const float* __restrict__ cC,
                         float* __restrict__ u) {
    int g = blockIdx.y;
    const float* cls = (g == 0) ? cA : (g == 1) ? cB : cC;
    __shared__ float Ct[64][65];
    __shared__ float At[64][65];
    int tid = threadIdx.x;
    int t0  = blockIdx.x * 64;
    for (int i = tid; i < 4096; i += 256) Ct[i >> 6][i & 63] = cls[i];
    for (int i = tid; i < 4096; i += 256) {
        int tok = i >> 6, r = i & 63;
        At[tok][r] = abc[(size_t)(t0 + tok) * 192 + g * 64 + r];
    }
    __syncthreads();
    int tx = tid & 15, ty = tid >> 4;
    float acc[4][4];
    #pragma unroll
    for (int i = 0; i < 4; i++)
        #pragma unroll
        for (int j = 0; j < 4; j++) acc[i][j] = 0.f;
    for (int r = 0; r < 64; r++) {
        float a[4], b[4];
        #pragma unroll
        for (int i = 0; i < 4; i++) a[i] = At[ty*4 + i][r];
        #pragma unroll
        for (int j = 0; j < 4; j++) b[j] = Ct[tx*4 + j][r];
        #pragma unroll
        for (int i = 0; i < 4; i++)
            #pragma unroll
            for (int j = 0; j < 4; j++) acc[i][j] = fmaf(a[i], b[j], acc[i][j]);
    }
    #pragma unroll
    for (int i = 0; i < 4; i++)
        #pragma unroll
        for (int j = 0; j < 4; j++)
            u[(size_t)(t0 + ty*4 + i) * 192 + g * 64 + tx*4 + j] = acc[i][j];
}

// ---------------- parallel triplet scan ----------------
__global__ void scan_seg_kernel(const float* __restrict__ u,
                                float* __restrict__ segout) {
    int b = blockIdx.x, s = blockIdx.y, c = threadIdx.x;
    int l0 = s * SEGL;
    int l1 = min(l0 + SEGL, LL - 1);
    const float* p = u + ((size_t)b * LL + l0) * 192;
    float pA = 0.f, pB = 0.f, pT = 0.f, AB = 0.f, BC = 0.f, S = 0.f, Cs = 0.f;
    #pragma unroll 4
    for (int l = l0; l < l1; l++) {
        float va = p[c], vb = p[64 + c], vc = p[128 + c];
        p += 192;
        S  = fmaf(vc, pT, S);
        BC = fmaf(vc, pB, BC);
        pT = fmaf(vb, pA, pT);
        AB = fmaf(vb, pA, AB);
        pB += vb;
        pA += va;
        Cs += vc;
    }
    float* o = segout + ((size_t)(b * NSEG + s) * 6) * 64 + c;
    o[0]   = pA;  o[64]  = pB;  o[128] = Cs;
    o[192] = AB;  o[256] = BC;  o[320] = S;
}

__global__ void scan_combine_kernel(const float* __restrict__ segout,
                                    const float* __restrict__ qn,
                                    const float* __restrict__ Wq,
                                    const float* __restrict__ bq,
                                    float* __restrict__ out) {
    int b = blockIdx.x, c = threadIdx.x;
    float PA = 0.f, PAB = 0.f, PE = 0.f, total = 0.f;
    #pragma unroll
    for (int s = 0; s < NSEG; s++) {
        const float* o = segout + ((size_t)(b * NSEG + s) * 6) * 64 + c;
        float A = o[0], B = o[64], C = o[128], AB = o[192], BC = o[256], S = o[320];
        total += S + C * (PE + PAB) + BC * PA;
        PE  = fmaf(B, PA, PE);
        PAB += AB;
        PA  += A;
    }
    float q = 0.f;
    const float* qr = qn + b * DD;
    #pragma unroll 8
    for (int k = 0; k < DD; k++) q = fmaf(qr[k], Wq[k * CC + c], q);
    const float inv_den = (float)(6.0 / (2047.0 * 2046.0 * 2045.0));
    out[b * CC + c] = total * inv_den + q + bq[c];
}

// ---------------- launch ----------------
extern "C" void kernel_launch(void* const* d_in, const int* in_sizes, int n_in,
                              void* d_out, int out_size) {
    const int*   ids       = (const int*)  d_in[0];
    const float* tok_emb   = (const float*)d_in[1];
    const float* pos_emb   = (const float*)d_in[2];
    const float* stem_ln_w = (const float*)d_in[3];
    const float* stem_ln_b = (const float*)d_in[4];
    const float* stem_w1   = (const float*)d_in[5];
    const float* stem_b1   = (const float*)d_in[6];
    const float* stem_w2   = (const float*)d_in[7];
    const float* stem_b2   = (const float*)d_in[8];
    const float* role_ln_w = (const float*)d_in[9];
    const float* role_ln_b = (const float*)d_in[10];
    const float* Wa        = (const float*)d_in[11];
    const float* Wb        = (const float*)d_in[12];
    const float* Wc        = (const float*)d_in[13];
    const float* class_a   = (const float*)d_in[14];
    const float* class_b   = (const float*)d_in[15];
    const float* class_c   = (const float*)d_in[16];
    const float* query_ln_w= (const float*)d_in[17];
    const float* query_ln_b= (const float*)d_in[18];
    const float* Wq        = (const float*)d_in[19];
    const float* bq        = (const float*)d_in[20];
    float* out = (float*)d_out;

    float *xp, *abcp, *up, *qnp, *segp;
    __half *xnp, *hp, *w1t, *w2t, *wt;
    cudaGetSymbolAddress((void**)&xp,   g_x);
    cudaGetSymbolAddress((void**)&xnp,  g_xn);
    cudaGetSymbolAddress((void**)&hp,   g_h);
    cudaGetSymbolAddress((void**)&abcp, g_abc);
    cudaGetSymbolAddress((void**)&up,   g_u);
    cudaGetSymbolAddress((void**)&qnp,  g_qn);
    cudaGetSymbolAddress((void**)&w1t,  g_w1t);
    cudaGetSymbolAddress((void**)&w2t,  g_w2t);
    cudaGetSymbolAddress((void**)&wt,   g_wt);
    cudaGetSymbolAddress((void**)&segp, g_seg);

    constexpr int SMV2 = 2 * (128 * 72 + 128 * 72) * 2;   // 73728 B
    constexpr int SM64 = 4 * (128 * 40 + 64 * 40) * 2;    // 61440 B
    cudaFuncSetAttribute(h16gemm2<1>,
                         cudaFuncAttributeMaxDynamicSharedMemorySize, SMV2);
    cudaFuncSetAttribute(h16gemm2<2>,
                         cudaFuncAttributeMaxDynamicSharedMemorySize, SMV2);
    cudaFuncSetAttribute(h16gemm_tanh<128,64>,
                         cudaFuncAttributeMaxDynamicSharedMemorySize, SM64);

    // 0. weight prep: fp16 transposes (smem-tiled)
    for (int i = 0; i < 2; i++) {
        transp_kernel<<<dim3(HH/32, DD/32), dim3(32,8)>>>(
            stem_w1 + (size_t)i*DD*HH, w1t + (size_t)i*HH*DD, DD, HH);
        transp_kernel<<<dim3(DD/32, HH/32), dim3(32,8)>>>(
            stem_w2 + (size_t)i*HH*DD, w2t + (size_t)i*DD*HH, HH, DD);
    }
    pack_w_kernel<<<(DD*64 + 255)/256, 256>>>(Wa, Wb, Wc, wt);

    // 1. embedding + LN0 fused
    embed_ln_kernel<<<MM, 128>>>(ids, tok_emb, pos_emb, stem_ln_w, stem_ln_b, xp, xnp);

    // 2. stem blocks
    for (int i = 0; i < 2; i++) {
        if (i > 0)
            ln_kernel<1><<<MM, 128>>>(xp, stem_ln_w + i*DD, stem_ln_b + i*DD, xnp, 1, 0);
        h16gemm2<1><<<dim3(HH/128, MM/128), 256, SMV2>>>(
            xnp, w1t + (size_t)i*HH*DD, stem_b1 + i*HH, hp, DD, HH);
        h16gemm2<2><<<dim3(DD/128, MM/128), 256, SMV2>>>(
            hp, w2t + (size_t)i*DD*HH, stem_b2 + i*DD, xp, HH, DD);
    }

    // 3. role LN (fp16 out)
    ln_kernel<1><<<MM, 128>>>(xp, role_ln_w, role_ln_b, xnp, 1, 0);

    // 4. abc = tanh(xn @ [Wa|Wb|Wc])
    h16gemm_tanh<128,64><<<dim3(3, MM/128), 256, SM64>>>(xnp, wt, abcp, DD, 192);

    // 5. u = abc @ class^T
    u_kernel<<<dim3(MM/64, 3), 256>>>(abcp, class_a, class_b, class_c, up);

    // 6. query LN (fp32 out)
    ln_kernel<0><<<BB, 128>>>(xp, query_ln_w, query_ln_b, qnp, LL, LL - 1);

    // 7. parallel triplet scan + combine
    scan_seg_kernel<<<dim3(BB, NSEG), 64>>>(up, segp);
    scan_combine_kernel<<<BB, CC>>>(segp, qnp, Wq, bq, out);
}

// round 8
// speedup vs baseline: 1.7211x; 1.0528x over previous
#include <cuda_runtime.h>
#include <cuda_fp16.h>
#include <math.h>

#define BB 8
#define LL 2048
#define DD 512
#define HH 1024
#define CC 64
#define MM (BB*LL)   // 16384
#define NSEG 32
#define SEGL 64

// ---------------- scratch (static device globals; no allocations) ----------------
__device__ float  g_x  [MM*DD];      // residual stream (fp32)
__device__ __half g_xn [MM*DD];      // LN outputs (fp16)
__device__ __half g_h  [MM*HH];      // GELU outputs (fp16)
__device__ float  g_abc[MM*192];     // tanh projections (fp32)
__device__ float  g_qn [BB*DD];
__device__ __half g_w1t[2*HH*DD];    // stem_w1 transposed [H][D] fp16
__device__ __half g_w2t[2*DD*HH];    // stem_w2 transposed [D][H] fp16
__device__ __half g_wt [192*DD];     // Wa|Wb|Wc transposed [192][D] fp16
__device__ float  g_seg[BB*NSEG*6*64];

// ---------------- PTX helpers ----------------
__device__ __forceinline__ void cp16g(void* dst, const void* src) {
    unsigned d = (unsigned)__cvta_generic_to_shared(dst);
    asm volatile("cp.async.cg.shared.global [%0], [%1], 16;\n" :: "r"(d), "l"(src));
}
__device__ __forceinline__ void cp_commit() {
    asm volatile("cp.async.commit_group;\n");
}
template<int N>
__device__ __forceinline__ void cp_wait() {
    asm volatile("cp.async.wait_group %0;\n" :: "n"(N));
}
__device__ __forceinline__ void ldsm4(unsigned& r0, unsigned& r1,
                                      unsigned& r2, unsigned& r3, unsigned addr) {
    asm volatile("ldmatrix.sync.aligned.m8n8.x4.shared.b16 {%0,%1,%2,%3}, [%4];"
                 : "=r"(r0), "=r"(r1), "=r"(r2), "=r"(r3) : "r"(addr));
}

// ---------------- fused embedding + first LN (fp16 xn out) ----------------
__global__ void embed_ln_kernel(const int* __restrict__ ids,
                                const float* __restrict__ tok,
                                const float* __restrict__ pos,
                                const float* __restrict__ lw,
                                const float* __restrict__ lb,
                                float* __restrict__ x,
                                __half* __restrict__ xn) {
    __shared__ float red[2][4];
    int t  = blockIdx.x;
    int id = ids[t];
    int l  = t & (LL - 1);
    float4 a = ((const float4*)(tok + (size_t)id * DD))[threadIdx.x];
    float4 p = ((const float4*)(pos + (size_t)l  * DD))[threadIdx.x];
    float4 v; v.x = a.x + p.x; v.y = a.y + p.y; v.z = a.z + p.z; v.w = a.w + p.w;
    ((float4*)(x + (size_t)t * DD))[threadIdx.x] = v;
    float s  = v.x + v.y + v.z + v.w;
    float s2 = v.x*v.x + v.y*v.y + v.z*v.z + v.w*v.w;
    #pragma unroll
    for (int o = 16; o; o >>= 1) {
        s  += __shfl_down_sync(0xffffffffu, s,  o);
        s2 += __shfl_down_sync(0xffffffffu, s2, o);
    }
    int warp = threadIdx.x >> 5, lane = threadIdx.x & 31;
    if (!lane) { red[0][warp] = s; red[1][warp] = s2; }
    __syncthreads();
    s  = red[0][0] + red[0][1] + red[0][2] + red[0][3];
    s2 = red[1][0] + red[1][1] + red[1][2] + red[1][3];
    float mean = s * (1.0f / DD);
    float var  = s2 * (1.0f / DD) - mean * mean;
    float inv  = rsqrtf(var + 1e-5f);
    int c = threadIdx.x * 4;
    float4 wv = *(const float4*)(lw + c);
    float4 bv = *(const float4*)(lb + c);
    __half2 h0 = __floats2half2_rn((v.x - mean) * inv * wv.x + bv.x,
                                   (v.y - mean) * inv * wv.y + bv.y);
    __half2 h1 = __floats2half2_rn((v.z - mean) * inv * wv.z + bv.z,
                                   (v.w - mean) * inv * wv.w + bv.w);
    *(__half2*)(xn + (size_t)t * DD + c)     = h0;
    *(__half2*)(xn + (size_t)t * DD + c + 2) = h1;
}

// ---------------- LayerNorm; HALF_OUT selects output type ----------------
template<int HALF_OUT>
__global__ void ln_kernel(const float* __restrict__ x,
                          const float* __restrict__ w,
                          const float* __restrict__ b,
                          void* __restrict__ outv,
                          int rowMul, int rowOff) {
    __shared__ float red[2][4];
    size_t inRow = (size_t)blockIdx.x * rowMul + rowOff;
    float4 v = ((const float4*)(x + inRow * DD))[threadIdx.x];
    float s  = v.x + v.y + v.z + v.w;
    float s2 = v.x*v.x + v.y*v.y + v.z*v.z + v.w*v.w;
    #pragma unroll
    for (int o = 16; o; o >>= 1) {
        s  += __shfl_down_sync(0xffffffffu, s,  o);
        s2 += __shfl_down_sync(0xffffffffu, s2, o);
    }
    int warp = threadIdx.x >> 5, lane = threadIdx.x & 31;
    if (!lane) { red[0][warp] = s; red[1][warp] = s2; }
    __syncthreads();
    s  = red[0][0] + red[0][1] + red[0][2] + red[0][3];
    s2 = red[1][0] + red[1][1] + red[1][2] + red[1][3];
    float mean = s * (1.0f / DD);
    float var  = s2 * (1.0f / DD) - mean * mean;
    float inv  = rsqrtf(var + 1e-5f);
    int c = threadIdx.x * 4;
    float4 wv = *(const float4*)(w + c);
    float4 bv = *(const float4*)(b + c);
    float o0 = (v.x - mean) * inv * wv.x + bv.x;
    float o1 = (v.y - mean) * inv * wv.y + bv.y;
    float o2 = (v.z - mean) * inv * wv.z + bv.z;
    float o3 = (v.w - mean) * inv * wv.w + bv.w;
    if (HALF_OUT) {
        __half* out = (__half*)outv;
        *(__half2*)(out + (size_t)blockIdx.x * DD + c)     = __floats2half2_rn(o0, o1);
        *(__half2*)(out + (size_t)blockIdx.x * DD + c + 2) = __floats2half2_rn(o2, o3);
    } else {
        float* out = (float*)outv;
        float4 o; o.x = o0; o.y = o1; o.z = o2; o.w = o3;
        ((float4*)(out + (size_t)blockIdx.x * DD))[threadIdx.x] = o;
    }
}

// ------- batched smem-tiled transpose: in[z][K][N] fp32 -> out[z][N][K] fp16 -------
__global__ void transp_kernel(const float* __restrict__ in,
                              __half* __restrict__ out, int K, int N) {
    __shared__ __half t[32][33];
    size_t zin  = (size_t)blockIdx.z * K * N;
    int n0 = blockIdx.x * 32, k0 = blockIdx.y * 32;
    int tx = threadIdx.x, ty = threadIdx.y;      // 32 x 8
    #pragma unroll
    for (int i = 0; i < 32; i += 8)
        t[ty + i][tx] = __float2half_rn(in[zin + (size_t)(k0 + ty + i) * N + n0 + tx]);
    __syncthreads();
    #pragma unroll
    for (int i = 0; i < 32; i += 8)
        out[zin + (size_t)(n0 + ty + i) * K + k0 + tx] = t[tx][ty + i];
}
// pack Wa|Wb|Wc -> [192][512] fp16 (row = class*64 + c)
__global__ void pack_w_kernel(const float* __restrict__ Wa,
                              const float* __restrict__ Wb,
                              const float* __restrict__ Wc,
                              __half* __restrict__ W) {
    int i = blockIdx.x * 256 + threadIdx.x;
    if (i >= DD * 64) return;
    int d = i >> 6, c = i & 63;
    W[(size_t)c * DD + d]         = __float2half_rn(Wa[i]);
    W[(size_t)(64 + c) * DD + d]  = __float2half_rn(Wb[i]);
    W[(size_t)(128 + c) * DD + d] = __float2half_rn(Wc[i]);
}

// ======= FP16 mma.sync GEMM: BK=64, ldmatrix fragments, 2-stage cp.async ======
// A fp16 [M][K] row-major, B fp16 [N][K] row-major. Tile 128xBN, 8 warps (4x2).
// EPI: 1 bias+exact GELU -> half, 2 bias+residual add -> fp32, 3 tanh -> fp32
template<int BN, int EPI>
__global__ __launch_bounds__(256, 2)
void h16gemm2(const __half* __restrict__ A, const __half* __restrict__ Bw,
              const float* __restrict__ bias, void* __restrict__ Cv,
              int K, int ldc) {
    constexpr int BM = 128, BK = 64;
    constexpr int LDA = BK + 8;                 // 72 halves = 144B
    constexpr int NI  = BN / 16;                // mma n8-pairs per warp
    constexpr int NP  = BN / 32;                // B ldmatrix.x4 per k16
    constexpr int ASZ = BM * LDA;
    constexpr int BSZ = BN * LDA;

    extern __shared__ __half smh[];
    __half* Asp = smh;
    __half* Bsp = smh + 2 * ASZ;

    const int tid  = threadIdx.x;
    const int lane = tid & 31, warp = tid >> 5;
    const int wr   = warp >> 1, wc = warp & 1;
    const int g    = lane >> 2, tig = lane & 3;
    const int rowBase = blockIdx.y * BM;
    const int colBase = blockIdx.x * BN;

    float acc[2][NI][4];
    #pragma unroll
    for (int mi = 0; mi < 2; mi++)
        #pragma unroll
        for (int ni = 0; ni < NI; ni++)
            #pragma unroll
            for (int r = 0; r < 4; r++) acc[mi][ni][r] = 0.f;

    unsigned aBase[2], bBase[NP];
    {
        unsigned a0 = (unsigned)__cvta_generic_to_shared(Asp);
        unsigned b0 = (unsigned)__cvta_generic_to_shared(Bsp);
        #pragma unroll
        for (int mi = 0; mi < 2; mi++) {
            int row = wr * 32 + mi * 16 + (lane & 15);
            int col = (lane >> 4) << 3;
            aBase[mi] = a0 + (row * LDA + col) * 2;
        }
        #pragma unroll
        for (int p = 0; p < NP; p++) {
            int row = wc * (BN / 2) + p * 16 + ((lane >> 4) << 3) + (lane & 7);
            int col = ((lane >> 3) & 1) << 3;
            bBase[p] = b0 + (row * LDA + col) * 2;
        }
    }

    const int nt = K / BK;

    auto issue = [&](int kt) {
        int st = kt & 1;
        int k0 = kt * BK;
        __half* As = Asp + st * ASZ;
        __half* Bs = Bsp + st * BSZ;
        #pragma unroll
        for (int it = 0; it < (BM * 8) / 256; it++) {
            int idx = tid + it * 256;
            int r = idx >> 3, u = (idx & 7) << 3;
            cp16g(As + r * LDA + u, A + (size_t)(rowBase + r) * K + k0 + u);
        }
        #pragma unroll
        for (int it = 0; it < (BN * 8) / 256; it++) {
            int idx = tid + it * 256;
            int r = idx >> 3, u = (idx & 7) << 3;
            cp16g(Bs + r * LDA + u, Bw + (size_t)(colBase + r) * K + k0 + u);
        }
    };

    issue(0); cp_commit();

    for (int kt = 0; kt < nt; kt++) {
        if (kt + 1 < nt) { issue(kt + 1); cp_commit(); cp_wait<1>(); }
        else             { cp_wait<0>(); }
        __syncthreads();

        unsigned stOffA = (unsigned)((kt & 1) * ASZ * 2);
        unsigned stOffB = (unsigned)((kt & 1) * BSZ * 2);

        #pragma unroll
        for (int kk = 0; kk < BK; kk += 16) {
            unsigned af[2][4];
            #pragma unroll
            for (int mi = 0; mi < 2; mi++)
                ldsm4(af[mi][0], af[mi][1], af[mi][2], af[mi][3],
                      aBase[mi] + stOffA + kk * 2);
            unsigned bf[NI][2];
            #pragma unroll
            for (int p = 0; p < NP; p++)
                ldsm4(bf[2*p][0], bf[2*p][1], bf[2*p+1][0], bf[2*p+1][1],
                      bBase[p] + stOffB + kk * 2);
            #pragma unroll
            for (int mi = 0; mi < 2; mi++)
                #pragma unroll
                for (int ni = 0; ni < NI; ni++) {
                    asm volatile(
                        "mma.sync.aligned.m16n8k16.row.col.f32.f16.f16.f32 "
                        "{%0,%1,%2,%3}, {%4,%5,%6,%7}, {%8,%9}, {%0,%1,%2,%3};"
                        : "+f"(acc[mi][ni][0]), "+f"(acc[mi][ni][1]),
                          "+f"(acc[mi][ni][2]), "+f"(acc[mi][ni][3])
                        : "r"(af[mi][0]), "r"(af[mi][1]), "r"(af[mi][2]), "r"(af[mi][3]),
                          "r"(bf[ni][0]), "r"(bf[ni][1]));
                }
        }
        __syncthreads();
    }

    #pragma unroll
    for (int mi = 0; mi < 2; mi++) {
        #pragma unroll
        for (int ni = 0; ni < NI; ni++) {
            int row = rowBase + wr * 32 + mi * 16 + g;
            int col = colBase + wc * (BN / 2) + ni * 8 + tig * 2;
            #pragma unroll
            for (int half_ = 0; half_ < 2; half_++) {
                int r = row + half_ * 8;
                float v0 = acc[mi][ni][half_ * 2 + 0];
                float v1 = acc[mi][ni][half_ * 2 + 1];
                if (EPI == 1) {                      // bias + exact GELU -> half
                    v0 += bias[col];  v1 += bias[col + 1];
                    __half* p = (__half*)Cv + (size_t)r * ldc + col;
                    *(__half2*)p = __floats2half2_rn(v0 * normcdff(v0),
                                                     v1 * normcdff(v1));
                } else if (EPI == 2) {               // bias + residual add -> fp32
                    float2* p = (float2*)((float*)Cv + (size_t)r * ldc + col);
                    float2 old = *p;
                    float2 o; o.x = old.x + v0 + bias[col];
                    o.y = old.y + v1 + bias[col + 1];
                    *p = o;
                } else {                             // tanh -> fp32
                    float2* p = (float2*)((float*)Cv + (size_t)r * ldc + col);
                    float2 o; o.x = tanhf(v0); o.y = tanhf(v1);
                    *p = o;
                }
            }
        }
    }
}

// ------- fused u = abc @ class^T + segment scan (one 64-token segment/block) -------
__global__ __launch_bounds__(256)
void uscan_kernel(const float* __restrict__ abc,
                  const float* __restrict__ cA,
                  const float* __restrict__ cB,
                  const float* __restrict__ cC,
                  float* __restrict__ segout) {
    // smem: At[64r][68tok], Ct[64r][68c], Ut[64tok][192]
    extern __shared__ float us[];
    float* At = us;                    // 64*68
    float* Ct = us + 64*68;            // 64*68
    float* Ut = us + 2*64*68;          // 64*192
    const int tid = threadIdx.x;
    const int t0  = blockIdx.x * 64;
    const int tx = tid & 15, ty = tid >> 4;

    for (int gi = 0; gi < 3; gi++) {
        const float* cls = (gi == 0) ? cA : (gi == 1) ? cB : cC;
        // Ct[r][c] = cls[c][r]; At[r][tok] = abc[t0+tok][gi*64+r]
        for (int i = tid; i < 4096; i += 256) {
            int c = i >> 6, r = i & 63;
            Ct[r * 68 + c] = cls[i];
        }
        for (int i = tid; i < 4096; i += 256) {
            int tok = i >> 6, r = i & 63;
            At[r * 68 + tok] = abc[(size_t)(t0 + tok) * 192 + gi * 64 + r];
        }
        __syncthreads();
        float acc[4][4];
        #pragma unroll
        for (int i = 0; i < 4; i++)
            #pragma unroll
            for (int j = 0; j < 4; j++) acc[i][j] = 0.f;
        for (int r = 0; r < 64; r++) {
            float4 a = *(const float4*)(At + r * 68 + ty * 4);
            float4 b = *(const float4*)(Ct + r * 68 + tx * 4);
            float av[4] = {a.x, a.y, a.z, a.w};
            float bv[4] = {b.x, b.y, b.z, b.w};
            #pragma unroll
            for (int i = 0; i < 4; i++)
                #pragma unroll
                for (int j = 0; j < 4; j++)
                    acc[i][j] = fmaf(av[i], bv[j], acc[i][j]);
        }
        #pragma unroll
        for (int i = 0; i < 4; i++)
            #pragma unroll
            for (int j = 0; j < 4; j++)
                Ut[(ty * 4 + i) * 192 + gi * 64 + tx * 4 + j] = acc[i][j];
        __syncthreads();
    }

    // in-block segment scan (threads 0..63), excluding within-batch token 2047
    if (tid < 64) {
        int c = tid;
        float pA = 0.f, pB = 0.f, pT = 0.f, AB = 0.f, BC = 0.f, S = 0.f, Cs = 0.f;
        int nTok = ((t0 & (LL - 1)) == LL - SEGL) ? SEGL - 1 : SEGL;
        #pragma unroll 4
        for (int i = 0; i < nTok; i++) {
            float va = Ut[i * 192 + c];
            float vb = Ut[i * 192 + 64 + c];
            float vc = Ut[i * 192 + 128 + c];
            S  = fmaf(vc, pT, S);
            BC = fmaf(vc, pB, BC);
            pT = fmaf(vb, pA, pT);
            AB = fmaf(vb, pA, AB);
            pB += vb;
            pA += va;
            Cs += vc;
        }
        int b = t0 >> 11;
        int s = (t0 & (LL - 1)) >> 6;
        float* o = segout + ((size_t)(b * NSEG + s) * 6) * 64 + c;
        o[0]   = pA;  o[64]  = pB;  o[128] = Cs;
        o[192] = AB;  o[256] = BC;  o[320] = S;
    }
}

// ---------------- phase 2: combine segments + query head ----------------
__global__ void scan_combine_kernel(const float* __restrict__ segout,
                                    const float* __restrict__ qn,
                                    const float* __restrict__ Wq,
                                    const float* __restrict__ bq,
                                    float* __restrict__ out) {
    int b = blockIdx.x, c = threadIdx.x;
    float PA = 0.f, PAB = 0.f, PE = 0.f, total = 0.f;
    #pragma unroll
    for (int s = 0; s < NSEG; s++) {
        const float* o = segout + ((size_t)(b * NSEG + s) * 6) * 64 + c;
        float A = o[0], B = o[64], C = o[128], AB = o[192], BC = o[256], S = o[320];
        total += S + C * (PE + PAB) + BC * PA;
        PE  = fmaf(B, PA, PE);
        PAB += AB;
        PA  += A;
    }
    float q = 0.f;
    const float* qr = qn + b * DD;
    #pragma unroll 8
    for (int k = 0; k < DD; k++) q = fmaf(qr[k], Wq[k * CC + c], q);
    const float inv_den = (float)(6.0 / (2047.0 * 2046.0 * 2045.0));
    out[b * CC + c] = total * inv_den + q + bq[c];
}

// ---------------- launch ----------------
extern "C" void kernel_launch(void* const* d_in, const int* in_sizes, int n_in,
                              void* d_out, int out_size) {
    const int*   ids       = (const int*)  d_in[0];
    const float* tok_emb   = (const float*)d_in[1];
    const float* pos_emb   = (const float*)d_in[2];
    const float* stem_ln_w = (const float*)d_in[3];
    const float* stem_ln_b = (const float*)d_in[4];
    const float* stem_w1   = (const float*)d_in[5];
    const float* stem_b1   = (const float*)d_in[6];
    const float* stem_w2   = (const float*)d_in[7];
    const float* stem_b2   = (const float*)d_in[8];
    const float* role_ln_w = (const float*)d_in[9];
    const float* role_ln_b = (const float*)d_in[10];
    const float* Wa        = (const float*)d_in[11];
    const float* Wb        = (const float*)d_in[12];
    const float* Wc        = (const float*)d_in[13];
    const float* class_a   = (const float*)d_in[14];
    const float* class_b   = (const float*)d_in[15];
    const float* class_c   = (const float*)d_in[16];
    const float* query_ln_w= (const float*)d_in[17];
    const float* query_ln_b= (const float*)d_in[18];
    const float* Wq        = (const float*)d_in[19];
    const float* bq        = (const float*)d_in[20];
    float* out = (float*)d_out;

    float *xp, *abcp, *qnp, *segp;
    __half *xnp, *hp, *w1t, *w2t, *wt;
    cudaGetSymbolAddress((void**)&xp,   g_x);
    cudaGetSymbolAddress((void**)&xnp,  g_xn);
    cudaGetSymbolAddress((void**)&hp,   g_h);
    cudaGetSymbolAddress((void**)&abcp, g_abc);
    cudaGetSymbolAddress((void**)&qnp,  g_qn);
    cudaGetSymbolAddress((void**)&w1t,  g_w1t);
    cudaGetSymbolAddress((void**)&w2t,  g_w2t);
    cudaGetSymbolAddress((void**)&wt,   g_wt);
    cudaGetSymbolAddress((void**)&segp, g_seg);

    constexpr int SMV2  = 2 * (128 * 72 + 128 * 72) * 2;   // 73728 B
    constexpr int SMV2R = 2 * (128 * 72 + 64 * 72) * 2;    // 55296 B
    constexpr int SMUS  = (2 * 64 * 68 + 64 * 192) * 4;    // 83968 B
    cudaFuncSetAttribute(h16gemm2<128,1>,
                         cudaFuncAttributeMaxDynamicSharedMemorySize, SMV2);
    cudaFuncSetAttribute(h16gemm2<128,2>,
                         cudaFuncAttributeMaxDynamicSharedMemorySize, SMV2);
    cudaFuncSetAttribute(h16gemm2<64,3>,
                         cudaFuncAttributeMaxDynamicSharedMemorySize, SMV2R);
    cudaFuncSetAttribute(uscan_kernel,
                         cudaFuncAttributeMaxDynamicSharedMemorySize, SMUS);

    // 0. weight prep: batched fp16 transposes + pack
    transp_kernel<<<dim3(HH/32, DD/32, 2), dim3(32,8)>>>(stem_w1, w1t, DD, HH);
    transp_kernel<<<dim3(DD/32, HH/32, 2), dim3(32,8)>>>(stem_w2, w2t, HH, DD);
    pack_w_kernel<<<(DD*64 + 255)/256, 256>>>(Wa, Wb, Wc, wt);

    // 1. embedding + LN0 fused
    embed_ln_kernel<<<MM, 128>>>(ids, tok_emb, pos_emb, stem_ln_w, stem_ln_b, xp, xnp);

    // 2. stem blocks
    for (int i = 0; i < 2; i++) {
        if (i > 0)
            ln_kernel<1><<<MM, 128>>>(xp, stem_ln_w + i*DD, stem_ln_b + i*DD, xnp, 1, 0);
        h16gemm2<128,1><<<dim3(HH/128, MM/128), 256, SMV2>>>(
            xnp, w1t + (size_t)i*HH*DD, stem_b1 + i*HH, hp, DD, HH);
        h16gemm2<128,2><<<dim3(DD/128, MM/128), 256, SMV2>>>(
            hp, w2t + (size_t)i*DD*HH, stem_b2 + i*DD, xp, HH, DD);
    }

    // 3. role LN (fp16 out)
    ln_kernel<1><<<MM, 128>>>(xp, role_ln_w, role_ln_b, xnp, 1, 0);

    // 4. abc = tanh(xn @ [Wa|Wb|Wc])  (ldmatrix path, BN=64, grid.x = 3 classes)
    h16gemm2<64,3><<<dim3(3, MM/128), 256, SMV2R>>>(xnp, wt, nullptr, abcp, DD, 192);

    // 5+7a. fused u GEMM + per-segment triplet scan
    uscan_kernel<<<MM/64, 256, SMUS>>>(abcp, class_a, class_b, class_c, segp);

    // 6. query LN (fp32 out)
    ln_kernel<0><<<BB, 128>>>(xp, query_ln_w, query_ln_b, qnp, LL, LL - 1);

    // 7b. combine segments + query head
    scan_combine_kernel<<<BB, CC>>>(segp, qnp, Wq, bq, out);
}